// round 7
// baseline (speedup 1.0000x reference)
#include <cuda_runtime.h>
#include <cuda_bf16.h>
#include <math_constants.h>
#include <stdint.h>

#define MROWS 256      // 4*64 query rows
#define DDIM 768
#define NKEYS 2048
#define RDIM 12
#define TOPK 16

#define K1P (3 * DDIM)     // 2304: K' for scores GEMM
#define K2P (3 * NKEYS)    // 6144: K' for output GEMM
#define SPLIT1 6
#define SPLIT2 16

// ---------------- scratch (static device globals; no allocation) ------------
// K-concatenated split-bf16 planes: A' = [Ah|Ah|Al], B' = [Bh|Bl|Bh]
__device__ __align__(16) __nv_bfloat16 g_posX  [MROWS * K1P];   // [Ph|Ph|Pl]
__device__ __align__(16) __nv_bfloat16 g_keysX [NKEYS * K1P];   // [Kh|Kl|Kh]
__device__ __align__(16) __nv_bfloat16 g_keysTX[DDIM * K2P];    // [KTh|KTl|KTh]
__device__ __align__(16) __nv_bfloat16 g_neiX  [MROWS * K2P];   // [Nh|Nh|Nl]
__device__ __align__(16) float g_adjsum [NKEYS * NKEYS];        // 16.8 MB
__device__ __align__(16) float g_scores6[SPLIT1 * MROWS * NKEYS];
__device__ __align__(16) float g_outp   [SPLIT2 * MROWS * DDIM];
__device__ float g_w[MROWS * TOPK];
__device__ int   g_idx[MROWS * TOPK];
__device__ int   g_used[NKEYS];

// ---------------- generic PTX helpers (no sm_103a-only features) ------------
__device__ __forceinline__ uint32_t smem_u32(const void* p) {
    uint32_t a;
    asm("{ .reg .u64 t; cvta.to.shared.u64 t, %1; cvt.u32.u64 %0, t; }"
        : "=r"(a) : "l"(p));
    return a;
}

#define SWZ128(off) ((off) ^ (((off) >> 3) & 0x70))

__device__ __forceinline__ void cpasync16(uint32_t saddr, const void* g) {
    asm volatile("cp.async.cg.shared.global [%0], [%1], 16;"
                 :: "r"(saddr), "l"(g) : "memory");
}
#define CP_COMMIT() asm volatile("cp.async.commit_group;" ::: "memory")
#define CP_WAIT(n)  asm volatile("cp.async.wait_group %0;" :: "n"(n) : "memory")

__device__ __forceinline__ void ldm_x4(uint32_t* r, uint32_t addr) {
    asm volatile("ldmatrix.sync.aligned.m8n8.x4.shared.b16 {%0,%1,%2,%3}, [%4];"
                 : "=r"(r[0]), "=r"(r[1]), "=r"(r[2]), "=r"(r[3]) : "r"(addr));
}
__device__ __forceinline__ void ldm_x2(uint32_t* r, uint32_t addr) {
    asm volatile("ldmatrix.sync.aligned.m8n8.x2.shared.b16 {%0,%1}, [%2];"
                 : "=r"(r[0]), "=r"(r[1]) : "r"(addr));
}

__device__ __forceinline__ void mma16816(float* c, const uint32_t* a, const uint32_t* b) {
    asm volatile(
        "mma.sync.aligned.m16n8k16.row.col.f32.bf16.bf16.f32 "
        "{%0,%1,%2,%3}, {%4,%5,%6,%7}, {%8,%9}, {%0,%1,%2,%3};"
        : "+f"(c[0]), "+f"(c[1]), "+f"(c[2]), "+f"(c[3])
        : "r"(a[0]), "r"(a[1]), "r"(a[2]), "r"(a[3]), "r"(b[0]), "r"(b[1]));
}

// bf16 hi/lo packing helpers
__device__ __forceinline__ unsigned pack_hi2(float a, float b) {
    return (unsigned)__bfloat16_as_ushort(__float2bfloat16(a)) |
           ((unsigned)__bfloat16_as_ushort(__float2bfloat16(b)) << 16);
}
__device__ __forceinline__ unsigned pack_lo2(float a, float b) {
    float ra = a - __bfloat162float(__float2bfloat16(a));
    float rb = b - __bfloat162float(__float2bfloat16(b));
    return (unsigned)__bfloat16_as_ushort(__float2bfloat16(ra)) |
           ((unsigned)__bfloat16_as_ushort(__float2bfloat16(rb)) << 16);
}

// ---------------- kernel 1: normalize keys -> [Kh|Kl|Kh]; zero used-mask ----
__global__ __launch_bounds__(256) void k_norm(const float* __restrict__ kp) {
    int n = blockIdx.x;
    int tid = threadIdx.x;
    const float* row = kp + n * DDIM;
    float ssq = 0.f;
    for (int i = tid; i < DDIM; i += 256) { float v = row[i]; ssq = fmaf(v, v, ssq); }
    #pragma unroll
    for (int o = 16; o > 0; o >>= 1) ssq += __shfl_xor_sync(0xffffffffu, ssq, o);
    __shared__ float sr[8];
    if ((tid & 31) == 0) sr[tid >> 5] = ssq;
    __syncthreads();
    float tot = sr[0] + sr[1] + sr[2] + sr[3] + sr[4] + sr[5] + sr[6] + sr[7];
    float inv = rsqrtf(tot + 1e-12f);
    for (int i = tid; i < DDIM; i += 256) {
        float v = row[i] * inv;
        __nv_bfloat16 h = __float2bfloat16(v);
        __nv_bfloat16 l = __float2bfloat16(v - __bfloat162float(h));
        g_keysX[n * K1P + i]            = h;   // seg0: hi
        g_keysX[n * K1P + DDIM + i]     = l;   // seg1: lo
        g_keysX[n * K1P + 2 * DDIM + i] = h;   // seg2: hi
    }
    if (tid == 0) g_used[n] = 0;
}

// ---------------- kernel 2: positions -> [Ph|Ph|Pl] -------------------------
__global__ __launch_bounds__(256) void k_prep(const float* __restrict__ pos) {
    int i4 = blockIdx.x * 256 + threadIdx.x;             // < 49152 float4s
    float4 v = ((const float4*)pos)[i4];
    uint2 H, L;
    H.x = pack_hi2(v.x, v.y); H.y = pack_hi2(v.z, v.w);
    L.x = pack_lo2(v.x, v.y); L.y = pack_lo2(v.z, v.w);
    int m = i4 / (DDIM / 4), c4 = i4 % (DDIM / 4);
    uint2* o = (uint2*)g_posX + (size_t)m * (K1P / 4);
    o[c4]                = H;    // seg0: hi
    o[DDIM / 4 + c4]     = H;    // seg1: hi
    o[2 * DDIM / 4 + c4] = L;    // seg2: lo
}

// ---------------- kernel 3: transpose keys -> [KTh|KTl|KTh] -----------------
__global__ __launch_bounds__(256) void k_transpose() {
    __shared__ __nv_bfloat16 th[32][33], tl[32][33];
    int tx = threadIdx.x & 31, ty = threadIdx.x >> 5;    // 32 x 8
    int d0 = blockIdx.x * 32, n0 = blockIdx.y * 32;
    #pragma unroll
    for (int i = 0; i < 32; i += 8) {
        int n = n0 + ty + i, d = d0 + tx;
        th[ty + i][tx] = g_keysX[n * K1P + d];           // hi plane
        tl[ty + i][tx] = g_keysX[n * K1P + DDIM + d];    // lo plane
    }
    __syncthreads();
    #pragma unroll
    for (int i = 0; i < 32; i += 8) {
        int d = d0 + ty + i, n = n0 + tx;
        __nv_bfloat16 h = th[tx][ty + i], l = tl[tx][ty + i];
        g_keysTX[d * K2P + n]             = h;   // seg0: hi
        g_keysTX[d * K2P + NKEYS + n]     = l;   // seg1: lo
        g_keysTX[d * K2P + 2 * NKEYS + n] = h;   // seg2: hi
    }
}

// ---------------- kernel 4: HMMA bf16 NT GEMM (plain, K-concat split) -------
// C_split[z](row0:+128, col0:+128) = A' @ B'^T over K'-split slice.
// Grid (N/128, M/128, nsplit); Kper multiple of 64; 256 threads (8 warps 2x4).
// Dynamic smem: 3 stages x 2 tiles x (128x64 bf16, SW128) = 98304 B.
#define TILE_B   16384
#define STAGE_B  32768
__global__ __launch_bounds__(256, 2)
void k_gemm(const __nv_bfloat16* __restrict__ Ap,
            const __nv_bfloat16* __restrict__ Bp,
            float* __restrict__ Cbase, int K, int Kper, int ldc) {
    extern __shared__ char smem[];
    const int tid = threadIdx.x, lane = tid & 31, wid = tid >> 5;
    const int warpM = wid >> 2, warpN = wid & 3;          // 2 x 4 warp grid
    const int col0 = blockIdx.x * 128, row0 = blockIdx.y * 128;
    const int kbeg = blockIdx.z * Kper;
    float* C = Cbase + (size_t)blockIdx.z * MROWS * ldc;
    const uint32_t sb0 = smem_u32(smem);

    float acc[4][4][4] = {};

    auto issue = [&](int slot, int k0) {
        uint32_t st = sb0 + slot * STAGE_B;
        #pragma unroll
        for (int j = 0; j < 4; j++) {
            int c = tid + 256 * j;                        // 0..1023
            int r = c >> 3, seg = c & 7;
            uint32_t so = SWZ128((uint32_t)(r * 128 + seg * 16));
            cpasync16(st + so,          Ap + (size_t)(row0 + r) * K + k0 + seg * 8);
            cpasync16(st + TILE_B + so, Bp + (size_t)(col0 + r) * K + k0 + seg * 8);
        }
    };

    const int nch = Kper >> 6;
    issue(0, kbeg); CP_COMMIT();
    if (nch > 1) { issue(1, kbeg + 64); CP_COMMIT(); }

    const int rA = lane & 15, selA = lane >> 4;
    const int rB = lane & 7,  selB = (lane >> 3) & 1;

    int slot = 0;
    for (int c = 0; c < nch; c++) {
        if (c + 1 < nch) CP_WAIT(1); else CP_WAIT(0);
        __syncthreads();
        if (c + 2 < nch) { issue((c + 2) % 3, kbeg + (c + 2) * 64); CP_COMMIT(); }
        uint32_t tA = sb0 + slot * STAGE_B, tB = tA + TILE_B;
        #pragma unroll
        for (int ks = 0; ks < 4; ks++) {
            uint32_t af[4][4], bf[4][2];
            #pragma unroll
            for (int tm = 0; tm < 4; tm++) {
                uint32_t off = SWZ128((uint32_t)((warpM * 64 + tm * 16 + rA) * 128 +
                                                 (ks * 16 + selA * 8) * 2));
                ldm_x4(af[tm], tA + off);
            }
            #pragma unroll
            for (int tn = 0; tn < 4; tn++) {
                uint32_t off = SWZ128((uint32_t)((warpN * 32 + tn * 8 + rB) * 128 +
                                                 (ks * 16 + selB * 8) * 2));
                ldm_x2(bf[tn], tB + off);
            }
            #pragma unroll
            for (int tm = 0; tm < 4; tm++)
                #pragma unroll
                for (int tn = 0; tn < 4; tn++)
                    mma16816(acc[tm][tn], af[tm], bf[tn]);
        }
        slot = (slot + 1) % 3;
        if (c + 1 < nch) __syncthreads();
    }

    // epilogue: fragment rows/cols -> C
    #pragma unroll
    for (int tm = 0; tm < 4; tm++) {
        int r0 = row0 + warpM * 64 + tm * 16 + (lane >> 2);
        #pragma unroll
        for (int tn = 0; tn < 4; tn++) {
            int col = col0 + warpN * 32 + tn * 8 + (lane & 3) * 2;
            *(float2*)&C[(size_t)r0 * ldc + col] =
                make_float2(acc[tm][tn][0], acc[tm][tn][1]);
            *(float2*)&C[(size_t)(r0 + 8) * ldc + col] =
                make_float2(acc[tm][tn][2], acc[tm][tn][3]);
        }
    }
}

// ---------------- kernel 5: top-16 + softmax (two-level warp argmax) --------
__device__ __forceinline__ unsigned long long tk_pack(float v, int idx) {
    unsigned u = __float_as_uint(v);
    u = (u & 0x80000000u) ? ~u : (u | 0x80000000u);
    return ((unsigned long long)u << 32) | (unsigned)(~idx);
}

__global__ __launch_bounds__(256) void k_topk() {
    int row = blockIdx.x;
    int tid = threadIdx.x, wid = tid >> 5, lane = tid & 31;
    __shared__ unsigned long long cand[8 * TOPK];
    __shared__ float svals[TOPK];
    __shared__ int   sidx[TOPK];

    // warp w owns n in [w*256, w*256+256); lane-coalesced; sum split buffers
    float v[8];
    #pragma unroll
    for (int j = 0; j < 8; j++) {
        int n = wid * 256 + lane + 32 * j;
        int o = row * NKEYS + n;
        float s = 0.f;
        #pragma unroll
        for (int z = 0; z < SPLIT1; z++) s += g_scores6[z * (MROWS * NKEYS) + o];
        v[j] = s;
    }
    // per-warp top-16 (no barriers)
    for (int it = 0; it < TOPK; it++) {
        unsigned long long best = tk_pack(v[0], wid * 256 + lane);
        #pragma unroll
        for (int j = 1; j < 8; j++) {
            unsigned long long c = tk_pack(v[j], wid * 256 + lane + 32 * j);
            if (c > best) best = c;
        }
        #pragma unroll
        for (int o = 16; o > 0; o >>= 1) {
            unsigned long long c = __shfl_xor_sync(0xffffffffu, best, o);
            if (c > best) best = c;
        }
        if (lane == 0) cand[wid * TOPK + it] = best;
        int local = (~(unsigned)(best & 0xffffffffull)) - wid * 256;
        if ((local & 31) == lane) v[local >> 5] = __int_as_float(0xff800000);
    }
    __syncthreads();
    // warp 0 merges the 128 candidates
    if (wid == 0) {
        unsigned long long c[4];
        #pragma unroll
        for (int j = 0; j < 4; j++) c[j] = cand[lane + 32 * j];
        for (int it = 0; it < TOPK; it++) {
            unsigned long long best = c[0];
            #pragma unroll
            for (int j = 1; j < 4; j++) if (c[j] > best) best = c[j];
            #pragma unroll
            for (int o = 16; o > 0; o >>= 1) {
                unsigned long long t = __shfl_xor_sync(0xffffffffu, best, o);
                if (t > best) best = t;
            }
            #pragma unroll
            for (int j = 0; j < 4; j++) if (c[j] == best) c[j] = 0ull;
            if (lane == 0) {
                unsigned u = (unsigned)(best >> 32);
                unsigned vb = (u & 0x80000000u) ? (u & 0x7fffffffu) : ~u;
                svals[it] = __uint_as_float(vb);
                sidx[it]  = (int)(~(unsigned)(best & 0xffffffffull));
            }
        }
        if (lane == 0) {
            float mx = svals[0], e[TOPK], sum = 0.f;
            #pragma unroll
            for (int i = 0; i < TOPK; i++) { e[i] = expf(svals[i] - mx); sum += e[i]; }
            float inv = 1.f / sum;
            #pragma unroll
            for (int i = 0; i < TOPK; i++) {
                g_w[row * TOPK + i]   = e[i] * inv;
                g_idx[row * TOPK + i] = sidx[i];
                g_used[sidx[i]] = 1;
            }
        }
    }
}

// ---------------- kernel 6: adj_sum over R (used rows only) -----------------
__global__ __launch_bounds__(256) void k_adjsum(const float* __restrict__ adj) {
    int row = blockIdx.x >> 1;
    if (!g_used[row]) return;
    int i = row * (NKEYS / 4) + (blockIdx.x & 1) * 256 + threadIdx.x;
    const float4* a = (const float4*)adj;
    const int stride = NKEYS * NKEYS / 4;
    float4 acc = make_float4(0.f, 0.f, 0.f, 0.f);
    #pragma unroll
    for (int r = 0; r < RDIM; r++) {
        float4 v = a[r * stride + i];
        acc.x += v.x; acc.y += v.y; acc.z += v.z; acc.w += v.w;
    }
    ((float4*)g_adjsum)[i] = acc;
}

// ---------------- kernel 7: nei gather -> [Nh|Nh|Nl] ------------------------
__global__ __launch_bounds__(256) void k_nei() {
    int row = blockIdx.x;
    int tid = threadIdx.x;
    __shared__ float sw[TOPK];
    __shared__ int   si[TOPK];
    if (tid < TOPK) { sw[tid] = g_w[row * TOPK + tid]; si[tid] = g_idx[row * TOPK + tid]; }
    __syncthreads();
    int n0 = blockIdx.y * (NKEYS / 2) + tid * 4;
    float4 a0 = make_float4(0.f, 0.f, 0.f, 0.f);
    #pragma unroll
    for (int kk = 0; kk < TOPK; kk++) {
        float wv = sw[kk];
        float4 v0 = *(const float4*)&g_adjsum[si[kk] * NKEYS + n0];
        a0.x = fmaf(wv, v0.x, a0.x); a0.y = fmaf(wv, v0.y, a0.y);
        a0.z = fmaf(wv, v0.z, a0.z); a0.w = fmaf(wv, v0.w, a0.w);
    }
    uint2 H, L;
    H.x = pack_hi2(a0.x, a0.y); H.y = pack_hi2(a0.z, a0.w);
    L.x = pack_lo2(a0.x, a0.y); L.y = pack_lo2(a0.z, a0.w);
    uint2* o = (uint2*)(g_neiX + (size_t)row * K2P);
    o[n0 / 4]                 = H;   // seg0: hi
    o[(NKEYS + n0) / 4]       = H;   // seg1: hi
    o[(2 * NKEYS + n0) / 4]   = L;   // seg2: lo
}

// ---------------- kernel 8: reduce split buffers -> d_out -------------------
__global__ __launch_bounds__(256) void k_reduce(float* __restrict__ out) {
    int i4 = blockIdx.x * 256 + threadIdx.x;       // < 49152 float4s
    const float4* p = (const float4*)g_outp;
    float4 a = make_float4(0.f, 0.f, 0.f, 0.f);
    #pragma unroll
    for (int z = 0; z < SPLIT2; z++) {
        float4 v = p[z * (MROWS * DDIM / 4) + i4];
        a.x += v.x; a.y += v.y; a.z += v.z; a.w += v.w;
    }
    ((float4*)out)[i4] = a;
}

// ---------------- launch ----------------------------------------------------
extern "C" void kernel_launch(void* const* d_in, const int* in_sizes, int n_in,
                              void* d_out, int out_size) {
    const float* positions  = (const float*)d_in[0];   // [4,64,768]
    const float* keys_param = (const float*)d_in[1];   // [2048,768]
    const float* adjacency  = (const float*)d_in[2];   // [12,2048,2048]
    float* out = (float*)d_out;                        // [4,64,768]

    __nv_bfloat16 *p_pX, *p_kX, *p_ktX, *p_nX;
    float *p_sc6, *p_outp;
    cudaGetSymbolAddress((void**)&p_pX,   g_posX);
    cudaGetSymbolAddress((void**)&p_kX,   g_keysX);
    cudaGetSymbolAddress((void**)&p_ktX,  g_keysTX);
    cudaGetSymbolAddress((void**)&p_nX,   g_neiX);
    cudaGetSymbolAddress((void**)&p_sc6,  g_scores6);
    cudaGetSymbolAddress((void**)&p_outp, g_outp);

    const int GEMM_SMEM = 3 * STAGE_B;      // 98304 bytes
    static int smem_set = 0;
    if (!smem_set) {
        cudaFuncSetAttribute(k_gemm, cudaFuncAttributeMaxDynamicSharedMemorySize,
                             GEMM_SMEM);
        smem_set = 1;
    }

    // 1. normalize keys -> K-concat planes; zero used mask
    k_norm<<<NKEYS, 256>>>(keys_param);
    // 2. positions -> K-concat planes
    k_prep<<<MROWS * DDIM / 4 / 256, 256>>>(positions);
    // 3. keys transpose -> K-concat planes (for GEMM2)
    {
        dim3 grid(DDIM / 32, NKEYS / 32);
        k_transpose<<<grid, dim3(256)>>>();
    }
    // 4. scores = positions @ keys^T  (M=256, N=2048, K'=2304, split-K=6)
    {
        dim3 grid(NKEYS / 128, MROWS / 128, SPLIT1);
        k_gemm<<<grid, 256, GEMM_SMEM>>>(p_pX, p_kX, p_sc6, K1P, K1P / SPLIT1, NKEYS);
    }
    // 5. top-16 + softmax (marks used rows)
    k_topk<<<MROWS, 256>>>();
    // 6. adjacency reduction over R (used rows only)
    k_adjsum<<<NKEYS * 2, 256>>>(adjacency);
    // 7. nei gather -> K-concat planes
    {
        dim3 grid(MROWS, 2);
        k_nei<<<grid, 256>>>();
    }
    // 8. out = nei @ keys  (M=256, N=768, K'=6144, split-K=16)
    {
        dim3 grid(DDIM / 128, MROWS / 128, SPLIT2);
        k_gemm<<<grid, 256, GEMM_SMEM>>>(p_nX, p_ktX, p_outp, K2P, K2P / SPLIT2, DDIM);
    }
    // 9. reduce split buffers into d_out
    k_reduce<<<MROWS * DDIM / 4 / 256, 256>>>(out);
}

// round 8
// speedup vs baseline: 1.1427x; 1.1427x over previous
#include <cuda_runtime.h>
#include <cuda_bf16.h>
#include <math_constants.h>
#include <stdint.h>

#define MROWS 256      // 4*64 query rows
#define DDIM 768
#define NKEYS 2048
#define RDIM 12
#define TOPK 16
#define SPLIT1 4
#define SPLIT2 12

// ---------------- scratch (static device globals; no allocation) ------------
__device__ __align__(16) __nv_bfloat16 g_keysh [NKEYS * DDIM];
__device__ __align__(16) __nv_bfloat16 g_keysl [NKEYS * DDIM];
__device__ __align__(16) __nv_bfloat16 g_keysTh[DDIM * NKEYS];
__device__ __align__(16) __nv_bfloat16 g_keysTl[DDIM * NKEYS];
__device__ __align__(16) __nv_bfloat16 g_posh  [MROWS * DDIM];
__device__ __align__(16) __nv_bfloat16 g_posl  [MROWS * DDIM];
__device__ __align__(16) __nv_bfloat16 g_neih  [MROWS * NKEYS];
__device__ __align__(16) __nv_bfloat16 g_neil  [MROWS * NKEYS];
__device__ __align__(16) float g_adjsum [NKEYS * NKEYS];          // 16.8 MB
__device__ __align__(16) float g_scores4[SPLIT1 * MROWS * NKEYS]; // split-K buffers
__device__ __align__(16) float g_outp   [SPLIT2 * MROWS * DDIM];  // split-K buffers
__device__ float g_w[MROWS * TOPK];
__device__ int   g_idx[MROWS * TOPK];
__device__ int   g_used[NKEYS];

// ---------------- generic PTX helpers (no sm_103a-only features) ------------
__device__ __forceinline__ uint32_t smem_u32(const void* p) {
    uint32_t a;
    asm("{ .reg .u64 t; cvta.to.shared.u64 t, %1; cvt.u32.u64 %0, t; }"
        : "=r"(a) : "l"(p));
    return a;
}

#define SWZ128(off) ((off) ^ (((off) >> 3) & 0x70))

__device__ __forceinline__ void cpasync16(uint32_t saddr, const void* g) {
    asm volatile("cp.async.cg.shared.global [%0], [%1], 16;"
                 :: "r"(saddr), "l"(g) : "memory");
}
#define CP_COMMIT() asm volatile("cp.async.commit_group;" ::: "memory")
#define CP_WAIT(n)  asm volatile("cp.async.wait_group %0;" :: "n"(n) : "memory")

__device__ __forceinline__ void ldm_x4(uint32_t* r, uint32_t addr) {
    asm volatile("ldmatrix.sync.aligned.m8n8.x4.shared.b16 {%0,%1,%2,%3}, [%4];"
                 : "=r"(r[0]), "=r"(r[1]), "=r"(r[2]), "=r"(r[3]) : "r"(addr));
}
__device__ __forceinline__ void ldm_x2(uint32_t* r, uint32_t addr) {
    asm volatile("ldmatrix.sync.aligned.m8n8.x2.shared.b16 {%0,%1}, [%2];"
                 : "=r"(r[0]), "=r"(r[1]) : "r"(addr));
}

__device__ __forceinline__ void mma16816(float* c, const uint32_t* a, const uint32_t* b) {
    asm volatile(
        "mma.sync.aligned.m16n8k16.row.col.f32.bf16.bf16.f32 "
        "{%0,%1,%2,%3}, {%4,%5,%6,%7}, {%8,%9}, {%0,%1,%2,%3};"
        : "+f"(c[0]), "+f"(c[1]), "+f"(c[2]), "+f"(c[3])
        : "r"(a[0]), "r"(a[1]), "r"(a[2]), "r"(a[3]), "r"(b[0]), "r"(b[1]));
}

// bf16 hi/lo packing helpers
__device__ __forceinline__ unsigned pack_hi2(float a, float b) {
    return (unsigned)__bfloat16_as_ushort(__float2bfloat16(a)) |
           ((unsigned)__bfloat16_as_ushort(__float2bfloat16(b)) << 16);
}
__device__ __forceinline__ unsigned pack_lo2(float a, float b) {
    float ra = a - __bfloat162float(__float2bfloat16(a));
    float rb = b - __bfloat162float(__float2bfloat16(b));
    return (unsigned)__bfloat16_as_ushort(__float2bfloat16(ra)) |
           ((unsigned)__bfloat16_as_ushort(__float2bfloat16(rb)) << 16);
}

// ---------------- kernel 1: fused keys-normalize + positions prep -----------
// blocks [0, NKEYS): normalize key row -> hi/lo planes; zero used-mask.
// blocks [NKEYS, NKEYS+192): convert positions chunk -> hi/lo planes.
__global__ __launch_bounds__(256) void k_norm_prep(const float* __restrict__ kp,
                                                   const float* __restrict__ pos) {
    int tid = threadIdx.x;
    if (blockIdx.x < NKEYS) {
        int n = blockIdx.x;
        const float* row = kp + n * DDIM;
        float ssq = 0.f;
        for (int i = tid; i < DDIM; i += 256) { float v = row[i]; ssq = fmaf(v, v, ssq); }
        #pragma unroll
        for (int o = 16; o > 0; o >>= 1) ssq += __shfl_xor_sync(0xffffffffu, ssq, o);
        __shared__ float sr[8];
        if ((tid & 31) == 0) sr[tid >> 5] = ssq;
        __syncthreads();
        float tot = sr[0] + sr[1] + sr[2] + sr[3] + sr[4] + sr[5] + sr[6] + sr[7];
        float inv = rsqrtf(tot + 1e-12f);
        for (int i = tid; i < DDIM; i += 256) {
            float v = row[i] * inv;
            __nv_bfloat16 h = __float2bfloat16(v);
            g_keysh[n * DDIM + i] = h;
            g_keysl[n * DDIM + i] = __float2bfloat16(v - __bfloat162float(h));
        }
        if (tid == 0) g_used[n] = 0;
    } else {
        int i4 = (blockIdx.x - NKEYS) * 256 + tid;       // < 49152 float4s
        float4 v = ((const float4*)pos)[i4];
        uint2 H, L;
        H.x = pack_hi2(v.x, v.y); H.y = pack_hi2(v.z, v.w);
        L.x = pack_lo2(v.x, v.y); L.y = pack_lo2(v.z, v.w);
        ((uint2*)g_posh)[i4] = H;
        ((uint2*)g_posl)[i4] = L;
    }
}

// ---------------- kernel 2: transpose keys planes -> keysT ------------------
__global__ __launch_bounds__(256) void k_transpose() {
    __shared__ __nv_bfloat16 th[32][33], tl[32][33];
    int tx = threadIdx.x & 31, ty = threadIdx.x >> 5;    // 32 x 8
    int d0 = blockIdx.x * 32, n0 = blockIdx.y * 32;
    #pragma unroll
    for (int i = 0; i < 32; i += 8) {
        int n = n0 + ty + i, d = d0 + tx;
        th[ty + i][tx] = g_keysh[n * DDIM + d];
        tl[ty + i][tx] = g_keysl[n * DDIM + d];
    }
    __syncthreads();
    #pragma unroll
    for (int i = 0; i < 32; i += 8) {
        int d = d0 + ty + i, n = n0 + tx;
        g_keysTh[d * NKEYS + n] = th[tx][ty + i];
        g_keysTl[d * NKEYS + n] = tl[tx][ty + i];
    }
}

// ---------------- kernel 3: HMMA bf16-split NT GEMM (Round-6 mainloop) ------
// C_split[z](row0:+128, col0:+128) = AhBh + AhBl + AlBh over this z's K-chunks.
// K chunks (64 each) are distributed over gridDim.z splits (uneven allowed).
// 256 threads (8 warps, 2x4). Dyn smem: 2 stages x 4 tiles x 16 KB = 131072 B.
#define TILE_B   16384
#define STAGE_B  65536
__global__ __launch_bounds__(256)
void k_gemm(const __nv_bfloat16* __restrict__ Ah, const __nv_bfloat16* __restrict__ Al,
            const __nv_bfloat16* __restrict__ Bh, const __nv_bfloat16* __restrict__ Bl,
            float* __restrict__ Cbase, int K, int ldc) {
    extern __shared__ char smem[];
    const int tid = threadIdx.x, lane = tid & 31, wid = tid >> 5;
    const int warpM = wid >> 2, warpN = wid & 3;          // 2 x 4 warp grid
    const int col0 = blockIdx.x * 128, row0 = blockIdx.y * 128;
    // uneven chunk split: CH chunks over gridDim.z parts
    const int CH = K >> 6, nz = gridDim.z, z = blockIdx.z;
    const int base = CH / nz, rem = CH - base * nz;
    const int nch  = base + (z < rem);
    const int kbeg = (z * base + (z < rem ? z : rem)) * 64;
    float* C = Cbase + (size_t)z * MROWS * ldc;
    const uint32_t sb0 = smem_u32(smem);

    float acc[4][4][4] = {};

    // stage loader: 4 tiles (Ah, Al, Bh, Bl), each 128 rows x 128 B, SW128
    auto issue = [&](int stage, int k0) {
        uint32_t st = sb0 + stage * STAGE_B;
        #pragma unroll
        for (int t = 0; t < 4; t++) {
            const __nv_bfloat16* src = (t == 0) ? Ah : (t == 1) ? Al
                                      : (t == 2) ? Bh : Bl;
            int rbase = (t < 2) ? row0 : col0;
            #pragma unroll
            for (int j = 0; j < 4; j++) {
                int c = tid + 256 * j;                    // 0..1023
                int r = c >> 3, seg = c & 7;
                uint32_t so = st + t * TILE_B + SWZ128((uint32_t)(r * 128 + seg * 16));
                cpasync16(so, src + (size_t)(rbase + r) * K + k0 + seg * 8);
            }
        }
    };

    issue(0, kbeg);
    CP_COMMIT();

    const int rA = lane & 15, selA = lane >> 4;
    const int rB = lane & 7,  selB = (lane >> 3) & 1;

    for (int c = 0; c < nch; c++) {
        if (c + 1 < nch) { issue((c + 1) & 1, kbeg + (c + 1) * 64); CP_COMMIT(); CP_WAIT(1); }
        else             { CP_WAIT(0); }
        __syncthreads();
        uint32_t st = sb0 + (c & 1) * STAGE_B;
        uint32_t tAh = st, tAl = st + TILE_B, tBh = st + 2 * TILE_B, tBl = st + 3 * TILE_B;
        #pragma unroll
        for (int ks = 0; ks < 4; ks++) {
            uint32_t ah[4][4], al[4][4], bh[4][2], bl[4][2];
            #pragma unroll
            for (int tm = 0; tm < 4; tm++) {
                uint32_t off = SWZ128((uint32_t)((warpM * 64 + tm * 16 + rA) * 128 +
                                                 (ks * 16 + selA * 8) * 2));
                ldm_x4(ah[tm], tAh + off);
                ldm_x4(al[tm], tAl + off);
            }
            #pragma unroll
            for (int tn = 0; tn < 4; tn++) {
                uint32_t off = SWZ128((uint32_t)((warpN * 32 + tn * 8 + rB) * 128 +
                                                 (ks * 16 + selB * 8) * 2));
                ldm_x2(bh[tn], tBh + off);
                ldm_x2(bl[tn], tBl + off);
            }
            #pragma unroll
            for (int tm = 0; tm < 4; tm++)
                #pragma unroll
                for (int tn = 0; tn < 4; tn++) {
                    mma16816(acc[tm][tn], ah[tm], bh[tn]);
                    mma16816(acc[tm][tn], ah[tm], bl[tn]);
                    mma16816(acc[tm][tn], al[tm], bh[tn]);
                }
        }
        __syncthreads();
    }

    // epilogue: fragment rows/cols -> C
    #pragma unroll
    for (int tm = 0; tm < 4; tm++) {
        int r0 = row0 + warpM * 64 + tm * 16 + (lane >> 2);
        #pragma unroll
        for (int tn = 0; tn < 4; tn++) {
            int col = col0 + warpN * 32 + tn * 8 + (lane & 3) * 2;
            *(float2*)&C[(size_t)r0 * ldc + col] =
                make_float2(acc[tm][tn][0], acc[tm][tn][1]);
            *(float2*)&C[(size_t)(r0 + 8) * ldc + col] =
                make_float2(acc[tm][tn][2], acc[tm][tn][3]);
        }
    }
}

// ---------------- kernel 4: top-16 + softmax (two-level warp argmax) --------
__device__ __forceinline__ unsigned long long tk_pack(float v, int idx) {
    unsigned u = __float_as_uint(v);
    u = (u & 0x80000000u) ? ~u : (u | 0x80000000u);
    return ((unsigned long long)u << 32) | (unsigned)(~idx);
}

__global__ __launch_bounds__(256) void k_topk() {
    int row = blockIdx.x;
    int tid = threadIdx.x, wid = tid >> 5, lane = tid & 31;
    __shared__ unsigned long long cand[8 * TOPK];
    __shared__ float svals[TOPK];
    __shared__ int   sidx[TOPK];

    // warp w owns n in [w*256, w*256+256); lane-coalesced; sum split buffers
    float v[8];
    #pragma unroll
    for (int j = 0; j < 8; j++) {
        int n = wid * 256 + lane + 32 * j;
        int o = row * NKEYS + n;
        float s = 0.f;
        #pragma unroll
        for (int z = 0; z < SPLIT1; z++) s += g_scores4[z * (MROWS * NKEYS) + o];
        v[j] = s;
    }
    // per-warp top-16 (no barriers)
    for (int it = 0; it < TOPK; it++) {
        unsigned long long best = tk_pack(v[0], wid * 256 + lane);
        #pragma unroll
        for (int j = 1; j < 8; j++) {
            unsigned long long c = tk_pack(v[j], wid * 256 + lane + 32 * j);
            if (c > best) best = c;
        }
        #pragma unroll
        for (int o = 16; o > 0; o >>= 1) {
            unsigned long long c = __shfl_xor_sync(0xffffffffu, best, o);
            if (c > best) best = c;
        }
        if (lane == 0) cand[wid * TOPK + it] = best;
        int local = (~(unsigned)(best & 0xffffffffull)) - wid * 256;
        if ((local & 31) == lane) v[local >> 5] = __int_as_float(0xff800000);
    }
    __syncthreads();
    // warp 0 merges the 128 candidates
    if (wid == 0) {
        unsigned long long c[4];
        #pragma unroll
        for (int j = 0; j < 4; j++) c[j] = cand[lane + 32 * j];
        for (int it = 0; it < TOPK; it++) {
            unsigned long long best = c[0];
            #pragma unroll
            for (int j = 1; j < 4; j++) if (c[j] > best) best = c[j];
            #pragma unroll
            for (int o = 16; o > 0; o >>= 1) {
                unsigned long long t = __shfl_xor_sync(0xffffffffu, best, o);
                if (t > best) best = t;
            }
            #pragma unroll
            for (int j = 0; j < 4; j++) if (c[j] == best) c[j] = 0ull;
            if (lane == 0) {
                unsigned u = (unsigned)(best >> 32);
                unsigned vb = (u & 0x80000000u) ? (u & 0x7fffffffu) : ~u;
                svals[it] = __uint_as_float(vb);
                sidx[it]  = (int)(~(unsigned)(best & 0xffffffffull));
            }
        }
        if (lane == 0) {
            float mx = svals[0], e[TOPK], sum = 0.f;
            #pragma unroll
            for (int i = 0; i < TOPK; i++) { e[i] = expf(svals[i] - mx); sum += e[i]; }
            float inv = 1.f / sum;
            #pragma unroll
            for (int i = 0; i < TOPK; i++) {
                g_w[row * TOPK + i]   = e[i] * inv;
                g_idx[row * TOPK + i] = sidx[i];
                g_used[sidx[i]] = 1;
            }
        }
    }
}

// ---------------- kernel 5: adj_sum over R (used rows only) -----------------
__global__ __launch_bounds__(256) void k_adjsum(const float* __restrict__ adj) {
    int row = blockIdx.x >> 1;
    if (!g_used[row]) return;
    int i = row * (NKEYS / 4) + (blockIdx.x & 1) * 256 + threadIdx.x;
    const float4* a = (const float4*)adj;
    const int stride = NKEYS * NKEYS / 4;
    float4 acc = make_float4(0.f, 0.f, 0.f, 0.f);
    #pragma unroll
    for (int r = 0; r < RDIM; r++) {
        float4 v = a[r * stride + i];
        acc.x += v.x; acc.y += v.y; acc.z += v.z; acc.w += v.w;
    }
    ((float4*)g_adjsum)[i] = acc;
}

// ---------------- kernel 6: nei gather -> hi/lo bf16 planes -----------------
__global__ __launch_bounds__(256) void k_nei() {
    int row = blockIdx.x;
    int tid = threadIdx.x;
    __shared__ float sw[TOPK];
    __shared__ int   si[TOPK];
    if (tid < TOPK) { sw[tid] = g_w[row * TOPK + tid]; si[tid] = g_idx[row * TOPK + tid]; }
    __syncthreads();
    int n0 = blockIdx.y * (NKEYS / 2) + tid * 4;
    float4 a0 = make_float4(0.f, 0.f, 0.f, 0.f);
    #pragma unroll
    for (int kk = 0; kk < TOPK; kk++) {
        float wv = sw[kk];
        float4 v0 = *(const float4*)&g_adjsum[si[kk] * NKEYS + n0];
        a0.x = fmaf(wv, v0.x, a0.x); a0.y = fmaf(wv, v0.y, a0.y);
        a0.z = fmaf(wv, v0.z, a0.z); a0.w = fmaf(wv, v0.w, a0.w);
    }
    uint2 H, L;
    H.x = pack_hi2(a0.x, a0.y); H.y = pack_hi2(a0.z, a0.w);
    L.x = pack_lo2(a0.x, a0.y); L.y = pack_lo2(a0.z, a0.w);
    *(uint2*)&g_neih[row * NKEYS + n0] = H;
    *(uint2*)&g_neil[row * NKEYS + n0] = L;
}

// ---------------- kernel 7: reduce split buffers -> d_out -------------------
__global__ __launch_bounds__(256) void k_reduce(float* __restrict__ out) {
    int i4 = blockIdx.x * 256 + threadIdx.x;       // < 49152 float4s
    const float4* p = (const float4*)g_outp;
    float4 a = make_float4(0.f, 0.f, 0.f, 0.f);
    #pragma unroll
    for (int z = 0; z < SPLIT2; z++) {
        float4 v = p[z * (MROWS * DDIM / 4) + i4];
        a.x += v.x; a.y += v.y; a.z += v.z; a.w += v.w;
    }
    ((float4*)out)[i4] = a;
}

// ---------------- launch ----------------------------------------------------
extern "C" void kernel_launch(void* const* d_in, const int* in_sizes, int n_in,
                              void* d_out, int out_size) {
    const float* positions  = (const float*)d_in[0];   // [4,64,768]
    const float* keys_param = (const float*)d_in[1];   // [2048,768]
    const float* adjacency  = (const float*)d_in[2];   // [12,2048,2048]
    float* out = (float*)d_out;                        // [4,64,768]

    __nv_bfloat16 *p_kh, *p_kl, *p_kth, *p_ktl, *p_ph, *p_pl, *p_nh, *p_nl;
    float *p_sc4, *p_outp;
    cudaGetSymbolAddress((void**)&p_kh,   g_keysh);
    cudaGetSymbolAddress((void**)&p_kl,   g_keysl);
    cudaGetSymbolAddress((void**)&p_kth,  g_keysTh);
    cudaGetSymbolAddress((void**)&p_ktl,  g_keysTl);
    cudaGetSymbolAddress((void**)&p_ph,   g_posh);
    cudaGetSymbolAddress((void**)&p_pl,   g_posl);
    cudaGetSymbolAddress((void**)&p_nh,   g_neih);
    cudaGetSymbolAddress((void**)&p_nl,   g_neil);
    cudaGetSymbolAddress((void**)&p_sc4,  g_scores4);
    cudaGetSymbolAddress((void**)&p_outp, g_outp);

    const int GEMM_SMEM = 2 * STAGE_B;      // 131072 bytes
    static int smem_set = 0;
    if (!smem_set) {
        cudaFuncSetAttribute(k_gemm, cudaFuncAttributeMaxDynamicSharedMemorySize,
                             GEMM_SMEM);
        smem_set = 1;
    }

    // 1. fused: normalize keys -> hi/lo (+used-mask reset) and positions -> hi/lo
    k_norm_prep<<<NKEYS + MROWS * DDIM / 4 / 256, 256>>>(keys_param, positions);
    // 2. keys transpose (for GEMM2's NT form)
    {
        dim3 grid(DDIM / 32, NKEYS / 32);
        k_transpose<<<grid, dim3(256)>>>();
    }
    // 3. scores = positions @ keys^T  (M=256, N=2048, K=768, split-K=4 -> 128 CTAs)
    {
        dim3 grid(NKEYS / 128, MROWS / 128, SPLIT1);
        k_gemm<<<grid, 256, GEMM_SMEM>>>(p_ph, p_pl, p_kh, p_kl, p_sc4,
                                         DDIM, NKEYS);
    }
    // 4. top-16 + softmax (marks used rows)
    k_topk<<<MROWS, 256>>>();
    // 5. adjacency reduction over R (used rows only)
    k_adjsum<<<NKEYS * 2, 256>>>(adjacency);
    // 6. nei gather -> hi/lo planes
    {
        dim3 grid(MROWS, 2);
        k_nei<<<grid, 256>>>();
    }
    // 7. out = nei @ keys  (M=256, N=768, K=2048, split-K=12 -> 144 CTAs)
    {
        dim3 grid(DDIM / 128, MROWS / 128, SPLIT2);
        k_gemm<<<grid, 256, GEMM_SMEM>>>(p_nh, p_nl, p_kth, p_ktl, p_outp,
                                         NKEYS, DDIM);
    }
    // 8. reduce split buffers into d_out
    k_reduce<<<MROWS * DDIM / 4 / 256, 256>>>(out);
}